// round 5
// baseline (speedup 1.0000x reference)
#include <cuda_runtime.h>
#include <math.h>

// Problem constants
#define BB   128          // batch
#define DD   128          // dim
#define KTOT 8194         // pos (2) + neg (8192)
#define KIN  8193         // idx[:,1:]
#define NMEM 100000
#define TAU_F 0.07f
#define KDT_F 3.0f
#define N4   (NMEM * (DD/4))   // float4 count per mem = 3,200,000

// Per-row partials: [0]=vcl_raw, [1]=soft_vcl_raw, [2]=icl_raw, [3]=soft_icl_raw
__device__ float g_part[4 * BB];

__device__ __forceinline__ float dot4(float4 a, float4 b) {
    return a.x*b.x + a.y*b.y + a.z*b.z + a.w*b.w;
}

// Block reduction of 4 values over exactly 512 threads (16 warps).
// Deterministic (fixed combine order). All threads get the result.
template <bool DO_MAX>
__device__ __forceinline__ void block_reduce4(float v[4], float* scr) {
    const int tid  = threadIdx.x;
    const int lane = tid & 31;
    const int warp = tid >> 5;
#pragma unroll
    for (int o = 16; o; o >>= 1) {
#pragma unroll
        for (int j = 0; j < 4; j++) {
            float ov = __shfl_xor_sync(0xffffffffu, v[j], o);
            v[j] = DO_MAX ? fmaxf(v[j], ov) : (v[j] + ov);
        }
    }
    __syncthreads();                 // protect scratch from previous round
    if (lane == 0) {
#pragma unroll
        for (int j = 0; j < 4; j++) scr[warp*4 + j] = v[j];
    }
    __syncthreads();
#pragma unroll
    for (int j = 0; j < 4; j++) v[j] = scr[j];
    for (int w = 1; w < 16; w++) {
#pragma unroll
        for (int j = 0; j < 4; j++) {
            float x = scr[w*4 + j];
            v[j] = DO_MAX ? fmaxf(v[j], x) : (v[j] + x);
        }
    }
    __syncthreads();
}

// ---------------------------------------------------------------------------
// Fused kernel: 1 CTA per batch row b.
// Gathers mem0[r], mem1[r] once per (b,k), computes 4 logit rows into SMEM,
// then does all softmax / KL / CE reductions in-block.
// ---------------------------------------------------------------------------
__global__ void __launch_bounds__(512, 1)
fused_logits_kernel(const float* __restrict__ emb0,
                    const float* __restrict__ emb1,
                    const float4* __restrict__ mem0,
                    const float4* __restrict__ mem1,
                    const int*   __restrict__ pos_idx,
                    const int*   __restrict__ neg_idx)
{
    extern __shared__ float sm[];
    float* s_cij = sm;                 // [KTOT]
    float* s_cji = sm + KTOT;          // [KTOT]
    float* s_ia  = sm + 2*KTOT;        // [KIN] (padded to KTOT)
    float* s_ib  = sm + 3*KTOT;        // [KIN]
    float* scr   = sm + 4*KTOT;        // [64] reduction scratch

    const int b    = blockIdx.x;
    const int tid  = threadIdx.x;
    const int lane = tid & 31;
    const int warp = tid >> 5;
    const int grp  = lane >> 3;        // quarter-warp id: 0..3  (one k each)
    const int gl   = lane & 7;         // lane within quarter-warp

    // Each lane owns float4 slots {gl, gl+8, gl+16, gl+24} of the 32-float4 row.
    const float4* e0p = reinterpret_cast<const float4*>(emb0) + b * 32;
    const float4* e1p = reinterpret_cast<const float4*>(emb1) + b * 32;
    float4 e0[4], e1[4];
#pragma unroll
    for (int i = 0; i < 4; i++) { e0[i] = e0p[gl + 8*i]; e1[i] = e1p[gl + 8*i]; }

    const float inv_tau = 1.0f / TAU_F;
    const int NGRP = (KTOT + 3) / 4;   // 2049 k-groups of 4

    for (int g = warp; g < NGRP; g += 16) {
        int  k     = g * 4 + grp;
        bool valid = (k < KTOT);
        int  r     = 0;
        if (valid) r = (k < 2) ? pos_idx[b*2 + k] : neg_idx[b*8192 + (k - 2)];
        const float4* M0 = mem0 + (size_t)r * 32;
        const float4* M1 = mem1 + (size_t)r * 32;

        float s01 = 0.f, s10 = 0.f, si0 = 0.f, si1 = 0.f;
#pragma unroll
        for (int i = 0; i < 4; i++) {
            float4 m0v = M0[gl + 8*i];     // 8 lanes -> one 128B line (coalesced)
            float4 m1v = M1[gl + 8*i];
            s01 += dot4(m0v, e1[i]);       // cij  = mem0 . emb1
            s10 += dot4(m1v, e0[i]);       // cji  = mem1 . emb0
            si0 += dot4(m0v, e0[i]);       // intra0 = mem0 . emb0
            si1 += dot4(m1v, e1[i]);       // intra1 = mem1 . emb1
        }
        // reduce within the 8-lane quarter-warp
#pragma unroll
        for (int o = 4; o; o >>= 1) {
            s01 += __shfl_xor_sync(0xffffffffu, s01, o);
            s10 += __shfl_xor_sync(0xffffffffu, s10, o);
            si0 += __shfl_xor_sync(0xffffffffu, si0, o);
            si1 += __shfl_xor_sync(0xffffffffu, si1, o);
        }
        if (valid) {
            if      (gl == 0)            s_cij[k]   = s01 * inv_tau;
            else if (gl == 1)            s_cji[k]   = s10 * inv_tau;
            else if (gl == 2 && k >= 1)  s_ia[k-1]  = si0 * inv_tau;
            else if (gl == 3 && k >= 1)  s_ib[k-1]  = si1 * inv_tau;
        }
    }
    __syncthreads();

    // ---- Phase A: row maxes (for stable logsumexp) ----
    float mv[4] = {-1e30f, -1e30f, -1e30f, -1e30f};
    for (int k = tid; k < KTOT; k += 512) {
        mv[0] = fmaxf(mv[0], s_cij[k]);
        mv[1] = fmaxf(mv[1], s_cji[k]);
    }
    for (int k = tid; k < KIN; k += 512) {
        mv[2] = fmaxf(mv[2], s_ia[k]);
        mv[3] = fmaxf(mv[3], s_ib[k]);
    }
    block_reduce4<true>(mv, scr);
    const float mA = mv[0], mB = mv[1], mIa = mv[2], mIb = mv[3];

    const float invT = 1.0f / KDT_F;

    // ---- Phase B1: inter exp-sums (Z at T=1 and T=KD_T) ----
    float sv[4] = {0.f, 0.f, 0.f, 0.f};
    for (int k = tid; k < KTOT; k += 512) {
        float a = s_cij[k] - mA, c = s_cji[k] - mB;
        sv[0] += expf(a);  sv[1] += expf(a * invT);
        sv[2] += expf(c);  sv[3] += expf(c * invT);
    }
    block_reduce4<false>(sv, scr);
    const float sA = sv[0], sAT = sv[1], sB = sv[2], sBT = sv[3];

    // ---- Phase B2: intra exp-sums ----
    float sv2[4] = {0.f, 0.f, 0.f, 0.f};
    for (int k = tid; k < KIN; k += 512) {
        float a = s_ia[k] - mIa, c = s_ib[k] - mIb;
        sv2[0] += expf(a);  sv2[1] += expf(a * invT);
        sv2[2] += expf(c);  sv2[3] += expf(c * invT);
    }
    block_reduce4<false>(sv2, scr);
    const float sIa = sv2[0], sIaT = sv2[1], sIb = sv2[2], sIbT = sv2[3];

    // ---- Phase C: KL weighted sums  (logZ terms cancel across the 2 directions) ----
    float wv[4] = {0.f, 0.f, 0.f, 0.f};
    for (int k = tid; k < KTOT; k += 512) {
        float a = s_cij[k], c = s_cji[k];
        wv[0] += expf((c - mB) * invT) * (c - a);   // kl(cij || cji): p_t from cji
        wv[1] += expf((a - mA) * invT) * (a - c);   // kl(cji || cij)
    }
    for (int k = tid; k < KIN; k += 512) {
        float a = s_ia[k], c = s_ib[k];
        wv[2] += expf((c - mIb) * invT) * (c - a);
        wv[3] += expf((a - mIa) * invT) * (a - c);
    }
    block_reduce4<false>(wv, scr);

    if (tid == 0) {
        float LA  = mA  + logf(sA);
        float LB  = mB  + logf(sB);
        float LIa = mIa + logf(sIa);
        float LIb = mIb + logf(sIb);
        // icl: -mean_b[ (lp0+lp1)/2 ] for cij and cji
        float icl_raw = -(0.5f * (s_cij[0] + s_cij[1]) - LA)
                        -(0.5f * (s_cji[0] + s_cji[1]) - LB);
        // kl sum * T^2 / T = T * (w/Z_t + w'/Z_s); /B applied in finalize
        float soft_icl_raw = KDT_F * (wv[0] / sBT + wv[1] / sAT);
        float vcl_raw = -(s_ia[0] - LIa) - (s_ib[0] - LIb);
        float soft_vcl_raw = KDT_F * (wv[2] / sIbT + wv[3] / sIaT);
        g_part[0*BB + b] = vcl_raw;
        g_part[1*BB + b] = soft_vcl_raw;
        g_part[2*BB + b] = icl_raw;
        g_part[3*BB + b] = soft_icl_raw;
    }
}

// ---------------------------------------------------------------------------
// Reduce the 128 per-row partials into the 4 scalar outputs. 1 block, 128 thr.
// ---------------------------------------------------------------------------
__global__ void finalize_kernel(float* __restrict__ out)
{
    __shared__ float scr[4];
    const int t = threadIdx.x;   // 128 threads
#pragma unroll
    for (int j = 0; j < 4; j++) {
        float v = g_part[j*BB + t];
#pragma unroll
        for (int o = 16; o; o >>= 1) v += __shfl_xor_sync(0xffffffffu, v, o);
        if ((t & 31) == 0) scr[t >> 5] = v;
        __syncthreads();
        if (t == 0) out[j] = (scr[0] + scr[1] + scr[2] + scr[3]) / (float)BB;
        __syncthreads();
    }
}

// ---------------------------------------------------------------------------
// Copy mem0, mem1 into the output buffer (new_mems baseline).
// ---------------------------------------------------------------------------
__global__ void copy_kernel(const float4* __restrict__ m0,
                            const float4* __restrict__ m1,
                            float4* __restrict__ dst)
{
    const int stride = gridDim.x * blockDim.x;
    for (int i = blockIdx.x * blockDim.x + threadIdx.x; i < N4; i += stride) {
        dst[i]      = m0[i];
        dst[N4 + i] = m1[i];
    }
}

// ---------------------------------------------------------------------------
// Momentum update of the p0 rows in the output copies.
// Last-wins on duplicate p0 indices (matches sequential scatter semantics).
// One block per b; warp0 -> net0, warp1 -> net1.
// ---------------------------------------------------------------------------
__global__ void update_kernel(const float* __restrict__ emb0,
                              const float* __restrict__ emb1,
                              const float4* __restrict__ mem0,
                              const float4* __restrict__ mem1,
                              const int*   __restrict__ pos_idx,
                              float* __restrict__ out)
{
    const int b = blockIdx.x;
    const int r = pos_idx[b * 2];
    for (int bp = b + 1; bp < BB; bp++)
        if (pos_idx[bp * 2] == r) return;          // a later b overwrites this row

    const int w    = threadIdx.x >> 5;             // 0: net0, 1: net1
    const int lane = threadIdx.x & 31;
    const float4* mem  = w ? mem1 : mem0;
    const float4* embp = reinterpret_cast<const float4*>(w ? emb1 : emb0);
    float4* dst = reinterpret_cast<float4*>(out + 4) + (size_t)w * N4;

    float4 m = mem[(size_t)r * 32 + lane];
    float4 e = embp[b * 32 + lane];
    float4 u;
    u.x = 0.5f * (m.x + e.x);   // MOM = 0.5
    u.y = 0.5f * (m.y + e.y);
    u.z = 0.5f * (m.z + e.z);
    u.w = 0.5f * (m.w + e.w);
    float s = u.x*u.x + u.y*u.y + u.z*u.z + u.w*u.w;
#pragma unroll
    for (int o = 16; o; o >>= 1) s += __shfl_xor_sync(0xffffffffu, s, o);
    float inv = 1.0f / sqrtf(s);
    u.x *= inv; u.y *= inv; u.z *= inv; u.w *= inv;
    dst[(size_t)r * 32 + lane] = u;
}

// ---------------------------------------------------------------------------
// Launch
// ---------------------------------------------------------------------------
extern "C" void kernel_launch(void* const* d_in, const int* in_sizes, int n_in,
                              void* d_out, int out_size)
{
    const float* emb0    = (const float*)d_in[0];
    const float* emb1    = (const float*)d_in[1];
    const float* mem0    = (const float*)d_in[2];
    const float* mem1    = (const float*)d_in[3];
    const int*   pos_idx = (const int*)  d_in[4];
    const int*   neg_idx = (const int*)  d_in[5];
    float* out = (float*)d_out;

    const int smem_bytes = (4 * KTOT + 64) * (int)sizeof(float);   // 131,360 B
    cudaFuncSetAttribute(fused_logits_kernel,
                         cudaFuncAttributeMaxDynamicSharedMemorySize, smem_bytes);

    // out layout: [vcl, soft_vcl, icl, soft_icl, new_mem0 (12.8M), new_mem1 (12.8M)]
    copy_kernel<<<2048, 256>>>((const float4*)mem0, (const float4*)mem1,
                               (float4*)(out + 4));
    fused_logits_kernel<<<BB, 512, smem_bytes>>>(emb0, emb1,
                                                 (const float4*)mem0,
                                                 (const float4*)mem1,
                                                 pos_idx, neg_idx);
    finalize_kernel<<<1, 128>>>(out);
    update_kernel<<<BB, 64>>>(emb0, emb1,
                              (const float4*)mem0, (const float4*)mem1,
                              pos_idx, out);
}

// round 6
// speedup vs baseline: 1.3597x; 1.3597x over previous
#include <cuda_runtime.h>
#include <math.h>

// Problem constants
#define BB    128
#define DD    128
#define KTOT  8194            // pos (2) + neg (8192)
#define NMEM  100000
#define TAU_INV 14.2857142857142857f   // 1/0.07
#define KDT_F 3.0f
#define N4    (NMEM * (DD/4)) // float4 per mem = 3,200,000
#define NGRP  ((KTOT + 3) / 4)         // 2049 k-groups of 4
#define SPLITS 8
#define COPYB  128            // copy CTAs (prefix of the big grid)

// Per-(b,split) partial sums, 12 each:
// j*3+0 = sum exp(v/T), j*3+1 = sum exp(v), j*3+2 = sum exp(v/T)*(v - other)
// j: 0=cij, 1=cji, 2=intra0, 3=intra1
__device__ float g_part2[BB][SPLITS][12];
// Per-b specials: [a0, c0, a1, c1, ia1, ib1] (logits at k=0,1)
__device__ float g_spec[BB][6];

__device__ __forceinline__ float dot4(float4 a, float4 b) {
    return a.x*b.x + a.y*b.y + a.z*b.z + a.w*b.w;
}

// ---------------------------------------------------------------------------
// Big kernel: CTAs [0,COPYB) stream-copy mem0/mem1 into out (DRAM-bound),
// CTAs [COPYB, COPYB+128*SPLITS) gather + compute all exp-sums inline
// (L2-bound; MUFU hidden under LDG latency). The two classes of CTAs run
// concurrently on the same SMs, overlapping DRAM and L2 bandwidth.
// ---------------------------------------------------------------------------
__global__ void __launch_bounds__(256, 4)
big_kernel(const float* __restrict__ emb0,
           const float* __restrict__ emb1,
           const float4* __restrict__ mem0,
           const float4* __restrict__ mem1,
           const int*   __restrict__ pos_idx,
           const int*   __restrict__ neg_idx,
           float* __restrict__ out)
{
    const int bid = blockIdx.x;

    if (bid < COPYB) {
        // ---- streaming copy: new_mems baseline ----
        float4* dst = reinterpret_cast<float4*>(out + 4);
        const int stride = COPYB * 256;
        for (int i = bid * 256 + threadIdx.x; i < N4; i += stride) {
            float4 a = mem0[i];
            float4 c = mem1[i];
            __stcs(dst + i,      a);   // evict-first: don't pollute L2
            __stcs(dst + N4 + i, c);
        }
        return;
    }

    // ---- gather CTA ----
    const int id    = bid - COPYB;
    const int b     = id & (BB - 1);
    const int split = id >> 7;           // 0..SPLITS-1

    const int tid  = threadIdx.x;
    const int lane = tid & 31;
    const int warp = tid >> 5;           // 0..7
    const int grp  = lane >> 3;          // quarter-warp: one k each
    const int gl   = lane & 7;
    const int j    = lane & 3;           // array this lane accumulates

    // emb rows in registers: lane owns float4 slots {gl, gl+8, gl+16, gl+24}
    const float4* e0p = reinterpret_cast<const float4*>(emb0) + b * 32;
    const float4* e1p = reinterpret_cast<const float4*>(emb1) + b * 32;
    float4 e0[4], e1[4];
#pragma unroll
    for (int i = 0; i < 4; i++) { e0[i] = e0p[gl + 8*i]; e1[i] = e1p[gl + 8*i]; }

    float accT = 0.f, acc1 = 0.f, accW = 0.f;

    for (int g = split * 8 + warp; g < NGRP; g += SPLITS * 8) {
        const int  k       = g * 4 + grp;
        const bool v_inter = (k < KTOT);
        int r = 0;
        if (v_inter) r = (k < 2) ? pos_idx[b*2 + k] : neg_idx[b*8192 + (k - 2)];
        const float4* M0 = mem0 + (size_t)r * 32;
        const float4* M1 = mem1 + (size_t)r * 32;

        float s01 = 0.f, s10 = 0.f, si0 = 0.f, si1 = 0.f;
#pragma unroll
        for (int i = 0; i < 4; i++) {
            float4 m0v = M0[gl + 8*i];   // 8 lanes -> one 128B line
            float4 m1v = M1[gl + 8*i];
            s01 += dot4(m0v, e1[i]);     // cij
            s10 += dot4(m1v, e0[i]);     // cji
            si0 += dot4(m0v, e0[i]);     // intra0
            si1 += dot4(m1v, e1[i]);     // intra1
        }
#pragma unroll
        for (int o = 4; o; o >>= 1) {
            s01 += __shfl_xor_sync(0xffffffffu, s01, o);
            s10 += __shfl_xor_sync(0xffffffffu, s10, o);
            si0 += __shfl_xor_sync(0xffffffffu, si0, o);
            si1 += __shfl_xor_sync(0xffffffffu, si1, o);
        }
        const float la  = s01 * TAU_INV;
        const float lc  = s10 * TAU_INV;
        const float lia = si0 * TAU_INV;
        const float lib = si1 * TAU_INV;

        if (g == 0) {                    // only split 0, warp 0 reaches g==0
            if (lane == 0) { g_spec[b][0] = la; g_spec[b][1] = lc; }   // k=0
            if (lane == 8) { g_spec[b][2] = la; g_spec[b][3] = lc;     // k=1
                             g_spec[b][4] = lia; g_spec[b][5] = lib; }
        }

        // lane's (value, other) pair for its array
        float v, o;
        if      (j == 0) { v = la;  o = lc;  }
        else if (j == 1) { v = lc;  o = la;  }
        else if (j == 2) { v = lia; o = lib; }
        else             { v = lib; o = lia; }
        const bool valid = (j < 2) ? v_inter : (v_inter && k >= 1);

        float e3 = valid ? __expf(v * (1.0f / KDT_F)) : 0.f;  // exp(v/3)
        accT += e3;
        acc1 += e3 * e3 * e3;            // exp(v) = exp(v/3)^3
        accW += e3 * (v - o);
    }

    // reduce lanes with equal (lane & 3): xor 4 folds the gl/gl+4 duplication
    // (exact x2, halved below); xor 8,16 fold the k-quarters.
#pragma unroll
    for (int o = 4; o <= 16; o <<= 1) {
        accT += __shfl_xor_sync(0xffffffffu, accT, o);
        acc1 += __shfl_xor_sync(0xffffffffu, acc1, o);
        accW += __shfl_xor_sync(0xffffffffu, accW, o);
    }

    __shared__ float sred[8][12];
    if (lane < 4) {
        sred[warp][lane*3 + 0] = accT * 0.5f;
        sred[warp][lane*3 + 1] = acc1 * 0.5f;
        sred[warp][lane*3 + 2] = accW * 0.5f;
    }
    __syncthreads();
    if (tid < 12) {
        float s = 0.f;
        for (int w = 0; w < 8; w++) s += sred[w][tid];   // fixed order
        g_part2[b][split][tid] = s;
    }
}

// ---------------------------------------------------------------------------
// Finalize: CTA 0 reduces partials into the 4 scalars; CTAs 1..32 apply the
// momentum update to the p0 rows of the output copies (last-wins dedup).
// ---------------------------------------------------------------------------
__global__ void __launch_bounds__(256)
finalize_kernel(const float* __restrict__ emb0,
                const float* __restrict__ emb1,
                const float4* __restrict__ mem0,
                const float4* __restrict__ mem1,
                const int*   __restrict__ pos_idx,
                float* __restrict__ out)
{
    if (blockIdx.x == 0) {
        const int t = threadIdx.x;
        float raw[4] = {0.f, 0.f, 0.f, 0.f};
        if (t < BB) {
            float s[12];
#pragma unroll
            for (int q = 0; q < 12; q++) {
                float acc = 0.f;
                for (int sp = 0; sp < SPLITS; sp++) acc += g_part2[t][sp][q];
                s[q] = acc;
            }
            const float sAT = s[0],  sA  = s[1],  w1 = s[2];
            const float sBT = s[3],  sB  = s[4],  w0 = s[5];
            const float sIaT= s[6],  sIa = s[7],  w3 = s[8];
            const float sIbT= s[9],  sIb = s[10], w2 = s[11];
            const float LA  = logf(sA),  LB  = logf(sB);
            const float LIa = logf(sIa), LIb = logf(sIb);
            const float a0 = g_spec[t][0], c0 = g_spec[t][1];
            const float a1 = g_spec[t][2], c1 = g_spec[t][3];
            const float ia1 = g_spec[t][4], ib1 = g_spec[t][5];
            raw[0] = -(ia1 - LIa) - (ib1 - LIb);                       // vcl
            raw[1] = KDT_F * (w2 / sIbT + w3 / sIaT);                  // soft_vcl
            raw[2] = -(0.5f*(a0+a1) - LA) - (0.5f*(c0+c1) - LB);       // icl
            raw[3] = KDT_F * (w0 / sBT + w1 / sAT);                    // soft_icl
        }
        __shared__ float scr[8][4];
#pragma unroll
        for (int q = 0; q < 4; q++) {
            float v = raw[q];
#pragma unroll
            for (int o = 16; o; o >>= 1) v += __shfl_xor_sync(0xffffffffu, v, o);
            if ((t & 31) == 0) scr[t >> 5][q] = v;
        }
        __syncthreads();
        if (t == 0) {
#pragma unroll
            for (int q = 0; q < 4; q++) {
                float v = 0.f;
                for (int w = 0; w < 8; w++) v += scr[w][q];
                out[q] = v / (float)BB;
            }
        }
        return;
    }

    // ---- momentum update: 256 warp tasks = (b, net) ----
    const int w    = (blockIdx.x - 1) * 8 + (threadIdx.x >> 5);  // 0..255
    const int lane = threadIdx.x & 31;
    const int b    = w & (BB - 1);
    const int net  = w >> 7;
    const int r    = pos_idx[b * 2];
    for (int bp = b + 1; bp < BB; bp++)
        if (pos_idx[bp * 2] == r) return;        // a later b overwrites

    const float4* mem  = net ? mem1 : mem0;
    const float4* embp = reinterpret_cast<const float4*>(net ? emb1 : emb0);
    float4* dst = reinterpret_cast<float4*>(out + 4) + (size_t)net * N4;

    float4 m = mem[(size_t)r * 32 + lane];
    float4 e = embp[b * 32 + lane];
    float4 u;
    u.x = 0.5f * (m.x + e.x);    // MOM = 0.5
    u.y = 0.5f * (m.y + e.y);
    u.z = 0.5f * (m.z + e.z);
    u.w = 0.5f * (m.w + e.w);
    float s2 = u.x*u.x + u.y*u.y + u.z*u.z + u.w*u.w;
#pragma unroll
    for (int o = 16; o; o >>= 1) s2 += __shfl_xor_sync(0xffffffffu, s2, o);
    const float inv = 1.0f / sqrtf(s2);
    u.x *= inv; u.y *= inv; u.z *= inv; u.w *= inv;
    dst[(size_t)r * 32 + lane] = u;
}

// ---------------------------------------------------------------------------
extern "C" void kernel_launch(void* const* d_in, const int* in_sizes, int n_in,
                              void* d_out, int out_size)
{
    const float* emb0    = (const float*)d_in[0];
    const float* emb1    = (const float*)d_in[1];
    const float* mem0    = (const float*)d_in[2];
    const float* mem1    = (const float*)d_in[3];
    const int*   pos_idx = (const int*)  d_in[4];
    const int*   neg_idx = (const int*)  d_in[5];
    float* out = (float*)d_out;

    // out layout: [vcl, soft_vcl, icl, soft_icl, new_mem0, new_mem1]
    big_kernel<<<COPYB + BB * SPLITS, 256>>>(emb0, emb1,
                                             (const float4*)mem0,
                                             (const float4*)mem1,
                                             pos_idx, neg_idx, out);
    finalize_kernel<<<33, 256>>>(emb0, emb1,
                                 (const float4*)mem0, (const float4*)mem1,
                                 pos_idx, out);
}